// round 16
// baseline (speedup 1.0000x reference)
#include <cuda_runtime.h>
#include <cuda_fp16.h>
#include <mma.h>
#include <math.h>
#include <stdint.h>
#include <stddef.h>

using namespace nvcuda;

#define NN 50000
#define NPAD 50048
#define EE 800000
#define FF 128
#define HBITS 21
#define HSIZE (1u<<HBITS)
#define HMASK (HSIZE-1u)
#define NEGINF __int_as_float(0xff800000)

// ---------------- device scratch ----------------
__device__ float    g_feat[(size_t)NN*FF];
__device__ float    g_xp2[(size_t)NN*FF];
__device__ __half   g_h_in[(size_t)NPAD*FF];
__device__ __half   g_h_z1[(size_t)NPAD*FF];
__device__ __half   g_h_z2[(size_t)NPAD*FF];
__device__ __half   g_Wh1[3*128*128];
__device__ __half   g_Wh2[3*128*128];
__device__ double   g_degd1[NN], g_degd2[NN];
__device__ float    g_dinv1[NN],  g_dinv2[NN];
__device__ float    g_dcinv1[NN], g_dcinv2[NN];
__device__ float    g_m[NN];
__device__ int      g_pt1[NN], g_pt2[NN];
__device__ int      g_c1[NN], g_c2[NN];
__device__ float    g_cut[EE];
__device__ int      g_s2[EE];
__device__ int      g_d2[EE];
__device__ float    g_w2[EE];
__device__ unsigned g_hash[HSIZE];
// CSR (double buffered)
__device__ int      g_rp1[NN+1], g_rp2[NN+1];
__device__ int      g_cnt1[NN],  g_cnt2[NN];
__device__ int      g_bsum[256];
__device__ int      g_total;
__device__ int      g_col1[EE],  g_col2[EE];
__device__ float    g_val1[EE],  g_val2[EE];

__device__ __forceinline__ float eluf(float v){ return v > 0.f ? v : expm1f(v); }

__device__ __forceinline__ uint2 f4_to_h4(float4 v){
    __half2 h0 = __floats2half2_rn(v.x, v.y);
    __half2 h1 = __floats2half2_rn(v.z, v.w);
    uint2 u;
    u.x = *reinterpret_cast<unsigned*>(&h0);
    u.y = *reinterpret_cast<unsigned*>(&h1);
    return u;
}

// ---------------- converts ----------------
__global__ void k_cvt(const float* __restrict__ in, __half* __restrict__ out){
    int i = blockIdx.x*blockDim.x + threadIdx.x;
    if (i >= NN*FF/4) return;
    float4 v = reinterpret_cast<const float4*>(in)[i];
    reinterpret_cast<uint2*>(out)[i] = f4_to_h4(v);
}
__global__ void k_cvtW(const float* __restrict__ in, __half* __restrict__ out){
    int i = blockIdx.x*blockDim.x + threadIdx.x;
    if (i >= 3*128*128/4) return;
    float4 v = reinterpret_cast<const float4*>(in)[i];
    reinterpret_cast<uint2*>(out)[i] = f4_to_h4(v);
}

// ---------------- CSR build (deg fused) ----------------
__global__ void k_count(const int* __restrict__ dst, const float* __restrict__ w,
                        int* __restrict__ cnt, double* __restrict__ degd){
    int e = blockIdx.x*blockDim.x + threadIdx.x;
    if (e >= EE) return;
    float wv = w[e];
    if (wv > 0.f){
        int d = dst[e];
        atomicAdd(&cnt[d], 1);
        atomicAdd(&degd[d], (double)wv);
    }
}
__global__ void k_scan1(const int* __restrict__ cnt, float* __restrict__ dcinv,
                        int* __restrict__ rp,
                        const double* __restrict__ degd, float* __restrict__ dinv){
    __shared__ int s[256];
    int t = threadIdx.x;
    int i = blockIdx.x*256 + t;
    int v = (i < NN) ? cnt[i] : 0;
    if (i < NN){
        dcinv[i] = v > 0 ? 1.0f/(float)v : 0.f;
        double d = degd[i];
        dinv[i] = d > 0.0 ? (float)(1.0/sqrt(d)) : 0.f;
    }
    s[t] = v; __syncthreads();
    #pragma unroll
    for (int off = 1; off < 256; off <<= 1){
        int tv = (t >= off) ? s[t-off] : 0;
        __syncthreads();
        s[t] += tv;
        __syncthreads();
    }
    if (i < NN) rp[i] = s[t] - v;
    if (t == 255) g_bsum[blockIdx.x] = s[255];
}
__global__ void k_scan2(){
    __shared__ int s[256];
    int t = threadIdx.x;
    int v = (t < 196) ? g_bsum[t] : 0;
    s[t] = v; __syncthreads();
    #pragma unroll
    for (int off = 1; off < 256; off <<= 1){
        int tv = (t >= off) ? s[t-off] : 0;
        __syncthreads();
        s[t] += tv;
        __syncthreads();
    }
    if (t < 196) g_bsum[t] = s[t] - v;
    if (t == 255) g_total = s[255];
}
__global__ void k_scan3(int* __restrict__ rp, int* __restrict__ pt){
    int i = blockIdx.x*256 + threadIdx.x;
    if (i < NN){
        rp[i] += g_bsum[blockIdx.x];
        g_m[i] = NEGINF;
        pt[i] = -1;
    }
    if (i == 0) rp[NN] = g_total;
}
__global__ void k_fill(const int* __restrict__ src, const int* __restrict__ dst,
                       const float* __restrict__ w,
                       const int* __restrict__ rp, int* __restrict__ cnt,
                       const float* __restrict__ dcinv,
                       const float* __restrict__ dinv,
                       int* __restrict__ col, float* __restrict__ val){
    int e = blockIdx.x*blockDim.x + threadIdx.x;
    if (e >= EE) return;
    int s = src[e], d = dst[e];
    float wv = w[e];
    float cut;
    if (wv > 0.f){
        int pos = rp[d] + atomicAdd(&cnt[d], 1);
        col[pos] = s;
        val[pos] = ((-dinv[d]) * dinv[s]) * wv;
        cut = wv * (dcinv[s] + dcinv[d]);
        atomicMax(reinterpret_cast<int*>(&g_m[s]), __float_as_int(cut));
    } else {
        cut = NEGINF;
    }
    g_cut[e] = cut;
}

// ---------------- prop core ----------------
struct PAcc { float a[8]; };

__device__ __forceinline__ void prop_edge(const uint4* __restrict__ z16,
                                          const int* __restrict__ col,
                                          const float* __restrict__ val,
                                          int e, int fl, PAcc& p){
    int   c = __ldg(&col[e]);
    float w = __ldg(&val[e]);
    uint4 u = __ldg(&z16[(size_t)c*16 + fl]);
    const __half2* hp = reinterpret_cast<const __half2*>(&u);
    float2 f0 = __half22float2(hp[0]);
    float2 f1 = __half22float2(hp[1]);
    float2 f2 = __half22float2(hp[2]);
    float2 f3 = __half22float2(hp[3]);
    p.a[0] = fmaf(w, f0.x, p.a[0]); p.a[1] = fmaf(w, f0.y, p.a[1]);
    p.a[2] = fmaf(w, f1.x, p.a[2]); p.a[3] = fmaf(w, f1.y, p.a[3]);
    p.a[4] = fmaf(w, f2.x, p.a[4]); p.a[5] = fmaf(w, f2.y, p.a[5]);
    p.a[6] = fmaf(w, f3.x, p.a[6]); p.a[7] = fmaf(w, f3.y, p.a[7]);
}

__device__ __forceinline__ uint4 pack_h8(const float* a){
    __half2 h0 = __floats2half2_rn(a[0], a[1]);
    __half2 h1 = __floats2half2_rn(a[2], a[3]);
    __half2 h2 = __floats2half2_rn(a[4], a[5]);
    __half2 h3 = __floats2half2_rn(a[6], a[7]);
    uint4 u;
    u.x = *reinterpret_cast<unsigned*>(&h0);
    u.y = *reinterpret_cast<unsigned*>(&h1);
    u.z = *reinterpret_cast<unsigned*>(&h2);
    u.w = *reinterpret_cast<unsigned*>(&h3);
    return u;
}

__device__ __forceinline__ void prop_body(const int* __restrict__ col,
                                          const float* __restrict__ val,
                                          const uint4* __restrict__ z16,
                                          int beg, int end, int half, int fl,
                                          float* outa){
    PAcc p, q;
    #pragma unroll
    for (int j = 0; j < 8; j++){ p.a[j] = 0.f; q.a[j] = 0.f; }
    int e = beg + half;
    for (; e + 2 < end; e += 4){
        prop_edge(z16, col, val, e,   fl, p);
        prop_edge(z16, col, val, e+2, fl, q);
    }
    if (e < end) prop_edge(z16, col, val, e, fl, p);
    #pragma unroll
    for (int j = 0; j < 8; j++){
        float s = p.a[j] + q.a[j];
        s += __shfl_xor_sync(0xFFFFFFFFu, s, 16);
        outa[j] = s;
    }
}

__global__ void __launch_bounds__(256) k_prop_a(const int* __restrict__ rp,
                                                const int* __restrict__ col,
                                                const float* __restrict__ val,
                                                const __half* __restrict__ zin_h,
                                                __half* __restrict__ zout_h){
    int node = (blockIdx.x*blockDim.x + threadIdx.x) >> 5;
    int lane = threadIdx.x & 31;
    int half = lane >> 4;
    int fl   = lane & 15;
    if (node >= NN) return;
    int beg = rp[node], end = rp[node+1];
    float a[8];
    prop_body(col, val, reinterpret_cast<const uint4*>(zin_h), beg, end, half, fl, a);
    if (lane < 16)
        reinterpret_cast<uint4*>(zout_h)[(size_t)node*16 + fl] = pack_h8(a);
}

__global__ void __launch_bounds__(256) k_prop_b(const int* __restrict__ rp,
                                                const int* __restrict__ col,
                                                const float* __restrict__ val,
                                                const __half* __restrict__ zin_h,
                                                const __half* __restrict__ z0_h,
                                                __half* __restrict__ zout_h){
    int node = (blockIdx.x*blockDim.x + threadIdx.x) >> 5;
    int lane = threadIdx.x & 31;
    int half = lane >> 4;
    int fl   = lane & 15;
    if (node >= NN) return;
    int beg = rp[node], end = rp[node+1];
    float a[8];
    prop_body(col, val, reinterpret_cast<const uint4*>(zin_h), beg, end, half, fl, a);
    if (lane < 16){
        uint4 u0 = __ldg(&reinterpret_cast<const uint4*>(z0_h)[(size_t)node*16 + fl]);
        const __half2* hp = reinterpret_cast<const __half2*>(&u0);
        float2 f0 = __half22float2(hp[0]);
        float2 f1 = __half22float2(hp[1]);
        float2 f2 = __half22float2(hp[2]);
        float2 f3 = __half22float2(hp[3]);
        a[0] = 2.f*a[0] - f0.x; a[1] = 2.f*a[1] - f0.y;
        a[2] = 2.f*a[2] - f1.x; a[3] = 2.f*a[3] - f1.y;
        a[4] = 2.f*a[4] - f2.x; a[5] = 2.f*a[5] - f2.y;
        a[6] = 2.f*a[6] - f3.x; a[7] = 2.f*a[7] - f3.y;
        reinterpret_cast<uint4*>(zout_h)[(size_t)node*16 + fl] = pack_h8(a);
    }
}

// ---------------- tensor-core GEMM, per-part smem staging (64KB) ----------------
#define GEMM_SMEM (2*128*128*2)
__global__ void __launch_bounds__(256) k_gemm_mma(const __half* __restrict__ hz0,
                                                  const __half* __restrict__ hz1,
                                                  const __half* __restrict__ hz2,
                                                  const __half* __restrict__ Wh,
                                                  const float* __restrict__ bv,
                                                  float* __restrict__ out){
    extern __shared__ __half smem[];
    __half* sW = smem;
    __half* sA = smem + 128*128;
    int tid  = threadIdx.x;
    int wid  = tid >> 5;
    int lane = tid & 31;
    int row0 = blockIdx.x * 128;

    wmma::fragment<wmma::accumulator, 16, 16, 16, float> acc[8];
    #pragma unroll
    for (int ns = 0; ns < 8; ns++) wmma::fill_fragment(acc[ns], 0.f);

    const __half* parts[3] = { hz0, hz1, hz2 };
    for (int part = 0; part < 3; part++){
        __syncthreads();
        {
            const uint4* Wg = reinterpret_cast<const uint4*>(Wh + (size_t)part*128*128);
            uint4* Ws = reinterpret_cast<uint4*>(sW);
            const uint4* Ag = reinterpret_cast<const uint4*>(parts[part] + (size_t)row0 * FF);
            uint4* As = reinterpret_cast<uint4*>(sA);
            #pragma unroll
            for (int q = 0; q < 8; q++){
                Ws[tid + 256*q] = Wg[tid + 256*q];
                As[tid + 256*q] = Ag[tid + 256*q];
            }
        }
        __syncthreads();
        const __half* ap = sA + (size_t)wid * 16 * 128;
        #pragma unroll
        for (int kk = 0; kk < 8; kk++){
            wmma::fragment<wmma::matrix_a, 16, 16, 16, __half, wmma::row_major> afr;
            wmma::load_matrix_sync(afr, ap + kk*16, 128);
            #pragma unroll
            for (int ns = 0; ns < 8; ns++){
                wmma::fragment<wmma::matrix_b, 16, 16, 16, __half, wmma::row_major> bfr;
                wmma::load_matrix_sync(bfr, sW + (size_t)(kk*16)*128 + ns*16, 128);
                wmma::mma_sync(acc[ns], afr, bfr, acc[ns]);
            }
        }
    }
    __syncthreads();

    float* sEp = reinterpret_cast<float*>(smem) + (size_t)wid * 16 * 128;
    #pragma unroll
    for (int ns = 0; ns < 8; ns++)
        wmma::store_matrix_sync(sEp + ns*16, acc[ns], 128, wmma::mem_row_major);
    __syncwarp();

    int r  = lane >> 1;
    int ch = (lane & 1) * 64;
    int grow = row0 + wid*16 + r;
    if (grow < NN){
        #pragma unroll
        for (int q = 0; q < 16; q++){
            int c = ch + q*4;
            float4 v = *reinterpret_cast<float4*>(sEp + r*128 + c);
            float4 b4 = *reinterpret_cast<const float4*>(bv + c);
            v.x = eluf(v.x + b4.x);
            v.y = eluf(v.y + b4.y);
            v.z = eluf(v.z + b4.z);
            v.w = eluf(v.w + b4.w);
            *reinterpret_cast<float4*>(out + (size_t)grow*FF + c) = v;
        }
    }
}

// ---------------- graclus matching ----------------
__global__ void k_partner(const int* __restrict__ src, const int* __restrict__ dst,
                          int* __restrict__ pt){
    int e = blockIdx.x*blockDim.x + threadIdx.x;
    if (e >= EE) return;
    float c = g_cut[e];
    int s = src[e];
    if (c > NEGINF && c == g_m[s])
        atomicMax(&pt[s], dst[e]);
}
__global__ void k_cluster(const int* __restrict__ pt, int* __restrict__ cl){
    int i = blockIdx.x*blockDim.x + threadIdx.x;
    if (i >= NN) return;
    int p = pt[i];
    int c = i;
    if (p >= 0 && p != i && pt[p] == i) c = min(i, p);
    cl[i] = c;
}

// ---------------- pool_x ----------------
__global__ void k_pool(const int* __restrict__ pt,
                       const float* __restrict__ x, float* __restrict__ xp,
                       __half* __restrict__ xph){
    int t = blockIdx.x*blockDim.x + threadIdx.x;
    int j = t >> 5, l = t & 31;
    if (j >= NN) return;
    int p = pt[j];
    bool mut = (p >= 0 && p != j && pt[p] == j);
    float4 o;
    if (mut && p < j){
        o = make_float4(0.f,0.f,0.f,0.f);
    } else {
        float4 a = reinterpret_cast<const float4*>(x + (size_t)j*FF)[l];
        if (mut){
            float4 b = reinterpret_cast<const float4*>(x + (size_t)p*FF)[l];
            a.x = fmaxf(a.x,b.x); a.y = fmaxf(a.y,b.y);
            a.z = fmaxf(a.z,b.z); a.w = fmaxf(a.w,b.w);
        }
        o = a;
    }
    if (xp)
        reinterpret_cast<float4*>(xp + (size_t)j*FF)[l] = o;
    if (xph)
        reinterpret_cast<uint2*>(xph)[(size_t)j*(FF/4) + l] = f4_to_h4(o);
}

// ---------------- pooled edges ----------------
__global__ void k_pool_edges(const int* __restrict__ src, const int* __restrict__ dst){
    int e = blockIdx.x*blockDim.x + threadIdx.x;
    if (e >= EE) return;
    int s = g_c1[src[e]], d = g_c1[dst[e]];
    g_s2[e] = s; g_d2[e] = d;
    float w = 0.f;
    if (s != d){
        unsigned key = (unsigned)s * (unsigned)NN + (unsigned)d;
        unsigned h = (key * 2654435761u) >> (32 - HBITS);
        h &= HMASK;
        while (true){
            unsigned old = atomicCAS(&g_hash[h], 0xFFFFFFFFu, key);
            if (old == 0xFFFFFFFFu){ w = 1.f; break; }
            if (old == key){ w = 0.f; break; }
            h = (h + 1u) & HMASK;
        }
    }
    g_w2[e] = w;
}

// ---------------- fused log_softmax + gather ----------------
__global__ void k_smax_gather(float* __restrict__ outp){
    int t = blockIdx.x*blockDim.x + threadIdx.x;
    int i = t >> 5, l = t & 31;
    if (i >= NN) return;
    int r = g_c2[g_c1[i]];
    float4 v = reinterpret_cast<const float4*>(g_xp2 + (size_t)r*FF)[l];
    float mx = fmaxf(fmaxf(v.x,v.y), fmaxf(v.z,v.w));
    #pragma unroll
    for (int off=16; off>0; off>>=1) mx = fmaxf(mx, __shfl_xor_sync(0xFFFFFFFFu, mx, off));
    float s = expf(v.x-mx)+expf(v.y-mx)+expf(v.z-mx)+expf(v.w-mx);
    #pragma unroll
    for (int off=16; off>0; off>>=1) s += __shfl_xor_sync(0xFFFFFFFFu, s, off);
    float lse = mx + logf(s);
    v.x -= lse; v.y -= lse; v.z -= lse; v.w -= lse;
    reinterpret_cast<float4*>(outp + (size_t)i*FF)[l] = v;
}

// ---------------- host ----------------
static void* symaddr(const void* s){ void* p = nullptr; cudaGetSymbolAddress(&p, s); return p; }

extern "C" void kernel_launch(void* const* d_in, const int* in_sizes, int n_in,
                              void* d_out, int out_size) {
    const float* x  = (const float*)d_in[0];
    const float* ew = (const float*)d_in[1];
    const float* W1 = (const float*)d_in[2];
    const float* b1 = (const float*)d_in[3];
    const float* W2 = (const float*)d_in[4];
    const float* b2 = (const float*)d_in[5];
    const int*   ei = (const int*)  d_in[6];
    const int* src = ei;
    const int* dst = ei + EE;
    float* outp = (float*)d_out;

    float*  feat = (float*)  symaddr(g_feat);
    float*  xp2  = (float*)  symaddr(g_xp2);
    __half* h_in = (__half*) symaddr(g_h_in);
    __half* h_z1 = (__half*) symaddr(g_h_z1);
    __half* h_z2 = (__half*) symaddr(g_h_z2);
    __half* Wh1  = (__half*) symaddr(g_Wh1);
    __half* Wh2  = (__half*) symaddr(g_Wh2);
    double* dgd1 = (double*) symaddr(g_degd1);
    double* dgd2 = (double*) symaddr(g_degd2);
    int*    cnt1 = (int*)    symaddr(g_cnt1);
    int*    cnt2 = (int*)    symaddr(g_cnt2);
    void*   hash = symaddr(g_hash);
    int*    c1   = (int*)    symaddr(g_c1);
    int*    c2   = (int*)    symaddr(g_c2);
    int*    s2   = (int*)    symaddr(g_s2);
    int*    d2   = (int*)    symaddr(g_d2);
    float*  w2   = (float*)  symaddr(g_w2);
    int*    rp1  = (int*)    symaddr(g_rp1);
    int*    rp2  = (int*)    symaddr(g_rp2);
    int*    col1 = (int*)    symaddr(g_col1);
    int*    col2 = (int*)    symaddr(g_col2);
    float*  val1 = (float*)  symaddr(g_val1);
    float*  val2 = (float*)  symaddr(g_val2);
    float*  di1  = (float*)  symaddr(g_dinv1);
    float*  di2  = (float*)  symaddr(g_dinv2);
    float*  dc1  = (float*)  symaddr(g_dcinv1);
    float*  dc2  = (float*)  symaddr(g_dcinv2);
    int*    pt1  = (int*)    symaddr(g_pt1);
    int*    pt2  = (int*)    symaddr(g_pt2);

    static cudaStream_t sB = nullptr, sC = nullptr;
    static cudaEvent_t evRoot, evPre, evFill, evC1, evB2, evCvt;
    if (!sB){
        cudaStreamCreate(&sB);
        cudaStreamCreate(&sC);
        cudaEventCreateWithFlags(&evRoot, cudaEventDisableTiming);
        cudaEventCreateWithFlags(&evPre,  cudaEventDisableTiming);
        cudaEventCreateWithFlags(&evFill, cudaEventDisableTiming);
        cudaEventCreateWithFlags(&evC1,  cudaEventDisableTiming);
        cudaEventCreateWithFlags(&evB2,  cudaEventDisableTiming);
        cudaEventCreateWithFlags(&evCvt, cudaEventDisableTiming);
        cudaFuncSetAttribute(k_gemm_mma, cudaFuncAttributeMaxDynamicSharedMemorySize, GEMM_SMEM);
    }

    const int EB = EE/256;
    const int NB = (NN+255)/256;
    const int PB = (NN*32+255)/256;
    const int GB = (NN+127)/128;
    const int CB = (NN*FF/4+255)/256;
    const int WB = (3*128*128/4+255)/256;

    // ===== fork point =====
    cudaMemsetAsync(cnt1, 0, NN*sizeof(int));
    cudaEventRecord(evRoot, 0);

    // ===== sC: degd memsets + fp16 mirrors =====
    cudaStreamWaitEvent(sC, evRoot, 0);
    cudaMemsetAsync(dgd1, 0, NN*sizeof(double), sC);
    cudaMemsetAsync(dgd2, 0, NN*sizeof(double), sC);
    cudaEventRecord(evPre, sC);
    k_cvt<<<CB,256,0,sC>>>(x, h_in);
    k_cvtW<<<WB,256,0,sC>>>(W1, Wh1);
    k_cvtW<<<WB,256,0,sC>>>(W2, Wh2);
    cudaEventRecord(evCvt, sC);

    // ===== A: block-1 CSR build =====
    cudaStreamWaitEvent(0, evPre, 0);
    k_count<<<EB,256>>>(dst, ew, cnt1, dgd1);
    k_scan1<<<NB,256>>>(cnt1, dc1, rp1, dgd1, di1);
    k_scan2<<<1,256>>>();
    k_scan3<<<NB,256>>>(rp1, pt1);
    cudaMemsetAsync(cnt1, 0, NN*sizeof(int));
    k_fill<<<EB,256>>>(src, dst, ew, rp1, cnt1, dc1, di1, col1, val1);
    cudaEventRecord(evFill, 0);

    // ===== B: matching + pooled-graph CSR build (hidden) =====
    cudaStreamWaitEvent(sB, evPre, 0);
    cudaStreamWaitEvent(sB, evFill, 0);
    k_partner<<<EB,256,0,sB>>>(src, dst, pt1);
    k_cluster<<<NB,256,0,sB>>>(pt1, c1);
    cudaEventRecord(evC1, sB);
    cudaMemsetAsync(hash, 0xFF, HSIZE*sizeof(unsigned), sB);
    k_pool_edges<<<EB,256,0,sB>>>(src, dst);
    cudaMemsetAsync(cnt2, 0, NN*sizeof(int), sB);
    k_count<<<EB,256,0,sB>>>(d2, w2, cnt2, dgd2);
    k_scan1<<<NB,256,0,sB>>>(cnt2, dc2, rp2, dgd2, di2);
    k_scan2<<<1,256,0,sB>>>();
    k_scan3<<<NB,256,0,sB>>>(rp2, pt2);
    cudaMemsetAsync(cnt2, 0, NN*sizeof(int), sB);
    k_fill<<<EB,256,0,sB>>>(s2, d2, w2, rp2, cnt2, dc2, di2, col2, val2);
    k_partner<<<EB,256,0,sB>>>(s2, d2, pt2);
    k_cluster<<<NB,256,0,sB>>>(pt2, c2);
    cudaEventRecord(evB2, sB);

    // ===== A: block-1 heavy chain =====
    cudaStreamWaitEvent(0, evCvt, 0);
    // --- SELF-TIMING: 3 clones of k_prop_a (identical args -> identical output,
    //     CSR already built on this stream; prop_a = (dur - 506.1)/3 ) ---
    k_prop_a<<<PB,256>>>(rp1, col1, val1, h_in, h_z1);
    k_prop_a<<<PB,256>>>(rp1, col1, val1, h_in, h_z1);
    k_prop_a<<<PB,256>>>(rp1, col1, val1, h_in, h_z1);
    // --- real chain ---
    k_prop_a<<<PB,256>>>(rp1, col1, val1, h_in, h_z1);
    k_prop_b<<<PB,256>>>(rp1, col1, val1, h_z1, h_in, h_z2);
    k_gemm_mma<<<GB,256,GEMM_SMEM>>>(h_in, h_z1, h_z2, Wh1, b1, feat);
    cudaStreamWaitEvent(0, evC1, 0);
    k_pool<<<PB,256>>>(pt1, feat, nullptr, h_in);

    // ===== A: block-2 heavy chain =====
    cudaStreamWaitEvent(0, evB2, 0);
    k_prop_a<<<PB,256>>>(rp2, col2, val2, h_in, h_z1);
    k_prop_b<<<PB,256>>>(rp2, col2, val2, h_z1, h_in, h_z2);
    k_gemm_mma<<<GB,256,GEMM_SMEM>>>(h_in, h_z1, h_z2, Wh2, b2, feat);
    k_pool<<<PB,256>>>(pt2, feat, xp2, nullptr);

    // ===== output =====
    k_smax_gather<<<PB,256>>>(outp);
}

// round 17
// speedup vs baseline: 1.3180x; 1.3180x over previous
#include <cuda_runtime.h>
#include <cuda_fp16.h>
#include <mma.h>
#include <math.h>
#include <stdint.h>
#include <stddef.h>

using namespace nvcuda;

#define NN 50000
#define NPAD 50048
#define EE 800000
#define FF 128
#define HBITS 21
#define HSIZE (1u<<HBITS)
#define HMASK (HSIZE-1u)
#define NEGINF __int_as_float(0xff800000)

// ---------------- device scratch ----------------
__device__ float    g_feat[(size_t)NN*FF];
__device__ float    g_xp2[(size_t)NN*FF];
__device__ __half   g_h_in[(size_t)NPAD*FF];
__device__ __half   g_h_z1[(size_t)NPAD*FF];
__device__ __half   g_h_z2[(size_t)NPAD*FF];
__device__ __half   g_Wh1[3*128*128];
__device__ __half   g_Wh2[3*128*128];
__device__ double   g_degd1[NN], g_degd2[NN];
__device__ float    g_dinv1[NN],  g_dinv2[NN];
__device__ float    g_dcinv1[NN], g_dcinv2[NN];
__device__ float    g_m[NN];
__device__ int      g_pt1[NN], g_pt2[NN];
__device__ int      g_c1[NN], g_c2[NN];
__device__ float    g_cut[EE];
__device__ int      g_s2[EE];
__device__ int      g_d2[EE];
__device__ float    g_w2[EE];
__device__ unsigned g_hash[HSIZE];
// CSR (double buffered)
__device__ int      g_rp1[NN+1], g_rp2[NN+1];
__device__ int      g_cnt1[NN],  g_cnt2[NN];
__device__ int      g_bsum[256];
__device__ int      g_total;
__device__ int      g_col1[EE],  g_col2[EE];
__device__ float    g_val1[EE],  g_val2[EE];

__device__ __forceinline__ float eluf(float v){ return v > 0.f ? v : expm1f(v); }

__device__ __forceinline__ uint2 f4_to_h4(float4 v){
    __half2 h0 = __floats2half2_rn(v.x, v.y);
    __half2 h1 = __floats2half2_rn(v.z, v.w);
    uint2 u;
    u.x = *reinterpret_cast<unsigned*>(&h0);
    u.y = *reinterpret_cast<unsigned*>(&h1);
    return u;
}

// ---------------- converts ----------------
__global__ void k_cvt(const float* __restrict__ in, __half* __restrict__ out){
    int i = blockIdx.x*blockDim.x + threadIdx.x;
    if (i >= NN*FF/4) return;
    float4 v = reinterpret_cast<const float4*>(in)[i];
    reinterpret_cast<uint2*>(out)[i] = f4_to_h4(v);
}
__global__ void k_cvtW(const float* __restrict__ in, __half* __restrict__ out){
    int i = blockIdx.x*blockDim.x + threadIdx.x;
    if (i >= 3*128*128/4) return;
    float4 v = reinterpret_cast<const float4*>(in)[i];
    reinterpret_cast<uint2*>(out)[i] = f4_to_h4(v);
}

// ---------------- CSR build (deg fused) ----------------
__global__ void k_count(const int* __restrict__ dst, const float* __restrict__ w,
                        int* __restrict__ cnt, double* __restrict__ degd){
    int e = blockIdx.x*blockDim.x + threadIdx.x;
    if (e >= EE) return;
    float wv = w[e];
    if (wv > 0.f){
        int d = dst[e];
        atomicAdd(&cnt[d], 1);
        atomicAdd(&degd[d], (double)wv);
    }
}
__global__ void k_scan1(const int* __restrict__ cnt, float* __restrict__ dcinv,
                        int* __restrict__ rp,
                        const double* __restrict__ degd, float* __restrict__ dinv){
    __shared__ int s[256];
    int t = threadIdx.x;
    int i = blockIdx.x*256 + t;
    int v = (i < NN) ? cnt[i] : 0;
    if (i < NN){
        dcinv[i] = v > 0 ? 1.0f/(float)v : 0.f;
        double d = degd[i];
        dinv[i] = d > 0.0 ? (float)(1.0/sqrt(d)) : 0.f;
    }
    s[t] = v; __syncthreads();
    #pragma unroll
    for (int off = 1; off < 256; off <<= 1){
        int tv = (t >= off) ? s[t-off] : 0;
        __syncthreads();
        s[t] += tv;
        __syncthreads();
    }
    if (i < NN) rp[i] = s[t] - v;
    if (t == 255) g_bsum[blockIdx.x] = s[255];
}
__global__ void k_scan2(){
    __shared__ int s[256];
    int t = threadIdx.x;
    int v = (t < 196) ? g_bsum[t] : 0;
    s[t] = v; __syncthreads();
    #pragma unroll
    for (int off = 1; off < 256; off <<= 1){
        int tv = (t >= off) ? s[t-off] : 0;
        __syncthreads();
        s[t] += tv;
        __syncthreads();
    }
    if (t < 196) g_bsum[t] = s[t] - v;
    if (t == 255) g_total = s[255];
}
__global__ void k_scan3(int* __restrict__ rp, int* __restrict__ pt){
    int i = blockIdx.x*256 + threadIdx.x;
    if (i < NN){
        rp[i] += g_bsum[blockIdx.x];
        g_m[i] = NEGINF;
        pt[i] = -1;
    }
    if (i == 0) rp[NN] = g_total;
}
__global__ void k_fill(const int* __restrict__ src, const int* __restrict__ dst,
                       const float* __restrict__ w,
                       const int* __restrict__ rp, int* __restrict__ cnt,
                       const float* __restrict__ dcinv,
                       const float* __restrict__ dinv,
                       int* __restrict__ col, float* __restrict__ val){
    int e = blockIdx.x*blockDim.x + threadIdx.x;
    if (e >= EE) return;
    int s = src[e], d = dst[e];
    float wv = w[e];
    float cut;
    if (wv > 0.f){
        int pos = rp[d] + atomicAdd(&cnt[d], 1);
        col[pos] = s;
        val[pos] = ((-dinv[d]) * dinv[s]) * wv;
        cut = wv * (dcinv[s] + dcinv[d]);
        atomicMax(reinterpret_cast<int*>(&g_m[s]), __float_as_int(cut));
    } else {
        cut = NEGINF;
    }
    g_cut[e] = cut;
}

// ---------------- prop core ----------------
struct PAcc { float a[8]; };

__device__ __forceinline__ void prop_edge(const uint4* __restrict__ z16,
                                          const int* __restrict__ col,
                                          const float* __restrict__ val,
                                          int e, int fl, PAcc& p){
    int   c = __ldg(&col[e]);
    float w = __ldg(&val[e]);
    uint4 u = __ldg(&z16[(size_t)c*16 + fl]);
    const __half2* hp = reinterpret_cast<const __half2*>(&u);
    float2 f0 = __half22float2(hp[0]);
    float2 f1 = __half22float2(hp[1]);
    float2 f2 = __half22float2(hp[2]);
    float2 f3 = __half22float2(hp[3]);
    p.a[0] = fmaf(w, f0.x, p.a[0]); p.a[1] = fmaf(w, f0.y, p.a[1]);
    p.a[2] = fmaf(w, f1.x, p.a[2]); p.a[3] = fmaf(w, f1.y, p.a[3]);
    p.a[4] = fmaf(w, f2.x, p.a[4]); p.a[5] = fmaf(w, f2.y, p.a[5]);
    p.a[6] = fmaf(w, f3.x, p.a[6]); p.a[7] = fmaf(w, f3.y, p.a[7]);
}

__device__ __forceinline__ uint4 pack_h8(const float* a){
    __half2 h0 = __floats2half2_rn(a[0], a[1]);
    __half2 h1 = __floats2half2_rn(a[2], a[3]);
    __half2 h2 = __floats2half2_rn(a[4], a[5]);
    __half2 h3 = __floats2half2_rn(a[6], a[7]);
    uint4 u;
    u.x = *reinterpret_cast<unsigned*>(&h0);
    u.y = *reinterpret_cast<unsigned*>(&h1);
    u.z = *reinterpret_cast<unsigned*>(&h2);
    u.w = *reinterpret_cast<unsigned*>(&h3);
    return u;
}

__device__ __forceinline__ void prop_body(const int* __restrict__ col,
                                          const float* __restrict__ val,
                                          const uint4* __restrict__ z16,
                                          int beg, int end, int half, int fl,
                                          float* outa){
    PAcc p, q;
    #pragma unroll
    for (int j = 0; j < 8; j++){ p.a[j] = 0.f; q.a[j] = 0.f; }
    int e = beg + half;
    for (; e + 2 < end; e += 4){
        prop_edge(z16, col, val, e,   fl, p);
        prop_edge(z16, col, val, e+2, fl, q);
    }
    if (e < end) prop_edge(z16, col, val, e, fl, p);
    #pragma unroll
    for (int j = 0; j < 8; j++){
        float s = p.a[j] + q.a[j];
        s += __shfl_xor_sync(0xFFFFFFFFu, s, 16);
        outa[j] = s;
    }
}

__global__ void __launch_bounds__(256) k_prop_a(const int* __restrict__ rp,
                                                const int* __restrict__ col,
                                                const float* __restrict__ val,
                                                const __half* __restrict__ zin_h,
                                                __half* __restrict__ zout_h){
    int node = (blockIdx.x*blockDim.x + threadIdx.x) >> 5;
    int lane = threadIdx.x & 31;
    int half = lane >> 4;
    int fl   = lane & 15;
    if (node >= NN) return;
    int beg = rp[node], end = rp[node+1];
    float a[8];
    prop_body(col, val, reinterpret_cast<const uint4*>(zin_h), beg, end, half, fl, a);
    if (lane < 16)
        reinterpret_cast<uint4*>(zout_h)[(size_t)node*16 + fl] = pack_h8(a);
}

__global__ void __launch_bounds__(256) k_prop_b(const int* __restrict__ rp,
                                                const int* __restrict__ col,
                                                const float* __restrict__ val,
                                                const __half* __restrict__ zin_h,
                                                const __half* __restrict__ z0_h,
                                                __half* __restrict__ zout_h){
    int node = (blockIdx.x*blockDim.x + threadIdx.x) >> 5;
    int lane = threadIdx.x & 31;
    int half = lane >> 4;
    int fl   = lane & 15;
    if (node >= NN) return;
    int beg = rp[node], end = rp[node+1];
    float a[8];
    prop_body(col, val, reinterpret_cast<const uint4*>(zin_h), beg, end, half, fl, a);
    if (lane < 16){
        uint4 u0 = __ldg(&reinterpret_cast<const uint4*>(z0_h)[(size_t)node*16 + fl]);
        const __half2* hp = reinterpret_cast<const __half2*>(&u0);
        float2 f0 = __half22float2(hp[0]);
        float2 f1 = __half22float2(hp[1]);
        float2 f2 = __half22float2(hp[2]);
        float2 f3 = __half22float2(hp[3]);
        a[0] = 2.f*a[0] - f0.x; a[1] = 2.f*a[1] - f0.y;
        a[2] = 2.f*a[2] - f1.x; a[3] = 2.f*a[3] - f1.y;
        a[4] = 2.f*a[4] - f2.x; a[5] = 2.f*a[5] - f2.y;
        a[6] = 2.f*a[6] - f3.x; a[7] = 2.f*a[7] - f3.y;
        reinterpret_cast<uint4*>(zout_h)[(size_t)node*16 + fl] = pack_h8(a);
    }
}

// ---------------- tensor-core GEMM, warp tile m32 x n64 ----------------
// 8 warps in 4(m) x 2(n): fragment loads per part per warp: 8kk*(2 afr + 4 bfr) = 48
#define GEMM_SMEM (2*128*128*2)
__global__ void __launch_bounds__(256) k_gemm_mma(const __half* __restrict__ hz0,
                                                  const __half* __restrict__ hz1,
                                                  const __half* __restrict__ hz2,
                                                  const __half* __restrict__ Wh,
                                                  const float* __restrict__ bv,
                                                  float* __restrict__ out){
    extern __shared__ __half smem[];
    __half* sW = smem;
    __half* sA = smem + 128*128;
    int tid  = threadIdx.x;
    int wid  = tid >> 5;
    int lane = tid & 31;
    int row0 = blockIdx.x * 128;
    int mq = wid & 3;          // m quarter: rows mq*32..mq*32+31
    int nh = wid >> 2;         // n half:   cols nh*64..nh*64+63

    wmma::fragment<wmma::accumulator, 16, 16, 16, float> acc[2][4];
    #pragma unroll
    for (int mi = 0; mi < 2; mi++)
        #pragma unroll
        for (int ni = 0; ni < 4; ni++)
            wmma::fill_fragment(acc[mi][ni], 0.f);

    const __half* parts[3] = { hz0, hz1, hz2 };
    for (int part = 0; part < 3; part++){
        __syncthreads();
        {
            const uint4* Wg = reinterpret_cast<const uint4*>(Wh + (size_t)part*128*128);
            uint4* Ws = reinterpret_cast<uint4*>(sW);
            const uint4* Ag = reinterpret_cast<const uint4*>(parts[part] + (size_t)row0 * FF);
            uint4* As = reinterpret_cast<uint4*>(sA);
            #pragma unroll
            for (int q = 0; q < 8; q++){
                Ws[tid + 256*q] = Wg[tid + 256*q];
                As[tid + 256*q] = Ag[tid + 256*q];
            }
        }
        __syncthreads();
        const __half* ap = sA + (size_t)(mq*32) * 128;
        const __half* wp = sW + nh*64;
        #pragma unroll
        for (int kk = 0; kk < 8; kk++){
            wmma::fragment<wmma::matrix_a, 16, 16, 16, __half, wmma::row_major> afr[2];
            wmma::load_matrix_sync(afr[0], ap + kk*16, 128);
            wmma::load_matrix_sync(afr[1], ap + 16*128 + kk*16, 128);
            #pragma unroll
            for (int ni = 0; ni < 4; ni++){
                wmma::fragment<wmma::matrix_b, 16, 16, 16, __half, wmma::row_major> bfr;
                wmma::load_matrix_sync(bfr, wp + (size_t)(kk*16)*128 + ni*16, 128);
                wmma::mma_sync(acc[0][ni], afr[0], bfr, acc[0][ni]);
                wmma::mma_sync(acc[1][ni], afr[1], bfr, acc[1][ni]);
            }
        }
    }
    __syncthreads();

    // epilogue: per-warp 32x64 fp32 region (8 warps * 8KB = 64KB, reuses smem)
    float* sEp = reinterpret_cast<float*>(smem) + (size_t)wid * 32 * 64;
    #pragma unroll
    for (int mi = 0; mi < 2; mi++)
        #pragma unroll
        for (int ni = 0; ni < 4; ni++)
            wmma::store_matrix_sync(sEp + mi*16*64 + ni*16, acc[mi][ni], 64, wmma::mem_row_major);
    __syncwarp();

    int grow = row0 + mq*32 + lane;
    int c0 = nh*64;
    if (grow < NN){
        #pragma unroll
        for (int q = 0; q < 16; q++){
            int c = q*4;
            float4 v = *reinterpret_cast<float4*>(sEp + lane*64 + c);
            float4 b4 = *reinterpret_cast<const float4*>(bv + c0 + c);
            v.x = eluf(v.x + b4.x);
            v.y = eluf(v.y + b4.y);
            v.z = eluf(v.z + b4.z);
            v.w = eluf(v.w + b4.w);
            *reinterpret_cast<float4*>(out + (size_t)grow*FF + c0 + c) = v;
        }
    }
}

// ---------------- graclus matching ----------------
__global__ void k_partner(const int* __restrict__ src, const int* __restrict__ dst,
                          int* __restrict__ pt){
    int e = blockIdx.x*blockDim.x + threadIdx.x;
    if (e >= EE) return;
    float c = g_cut[e];
    int s = src[e];
    if (c > NEGINF && c == g_m[s])
        atomicMax(&pt[s], dst[e]);
}
__global__ void k_cluster(const int* __restrict__ pt, int* __restrict__ cl){
    int i = blockIdx.x*blockDim.x + threadIdx.x;
    if (i >= NN) return;
    int p = pt[i];
    int c = i;
    if (p >= 0 && p != i && pt[p] == i) c = min(i, p);
    cl[i] = c;
}

// ---------------- pool_x ----------------
__global__ void k_pool(const int* __restrict__ pt,
                       const float* __restrict__ x, float* __restrict__ xp,
                       __half* __restrict__ xph){
    int t = blockIdx.x*blockDim.x + threadIdx.x;
    int j = t >> 5, l = t & 31;
    if (j >= NN) return;
    int p = pt[j];
    bool mut = (p >= 0 && p != j && pt[p] == j);
    float4 o;
    if (mut && p < j){
        o = make_float4(0.f,0.f,0.f,0.f);
    } else {
        float4 a = reinterpret_cast<const float4*>(x + (size_t)j*FF)[l];
        if (mut){
            float4 b = reinterpret_cast<const float4*>(x + (size_t)p*FF)[l];
            a.x = fmaxf(a.x,b.x); a.y = fmaxf(a.y,b.y);
            a.z = fmaxf(a.z,b.z); a.w = fmaxf(a.w,b.w);
        }
        o = a;
    }
    if (xp)
        reinterpret_cast<float4*>(xp + (size_t)j*FF)[l] = o;
    if (xph)
        reinterpret_cast<uint2*>(xph)[(size_t)j*(FF/4) + l] = f4_to_h4(o);
}

// ---------------- pooled edges + fused block-2 count/deg ----------------
__global__ void k_pool_edges(const int* __restrict__ src, const int* __restrict__ dst,
                             int* __restrict__ cnt2, double* __restrict__ degd2){
    int e = blockIdx.x*blockDim.x + threadIdx.x;
    if (e >= EE) return;
    int s = g_c1[src[e]], d = g_c1[dst[e]];
    g_s2[e] = s; g_d2[e] = d;
    float w = 0.f;
    if (s != d){
        unsigned key = (unsigned)s * (unsigned)NN + (unsigned)d;
        unsigned h = (key * 2654435761u) >> (32 - HBITS);
        h &= HMASK;
        while (true){
            unsigned old = atomicCAS(&g_hash[h], 0xFFFFFFFFu, key);
            if (old == 0xFFFFFFFFu){ w = 1.f; break; }
            if (old == key){ w = 0.f; break; }
            h = (h + 1u) & HMASK;
        }
    }
    g_w2[e] = w;
    if (w > 0.f){                      // fused count2 + degd2 (weight is exactly 1.0)
        atomicAdd(&cnt2[d], 1);
        atomicAdd(&degd2[d], 1.0);
    }
}

// ---------------- fused log_softmax + gather ----------------
__global__ void k_smax_gather(float* __restrict__ outp){
    int t = blockIdx.x*blockDim.x + threadIdx.x;
    int i = t >> 5, l = t & 31;
    if (i >= NN) return;
    int r = g_c2[g_c1[i]];
    float4 v = reinterpret_cast<const float4*>(g_xp2 + (size_t)r*FF)[l];
    float mx = fmaxf(fmaxf(v.x,v.y), fmaxf(v.z,v.w));
    #pragma unroll
    for (int off=16; off>0; off>>=1) mx = fmaxf(mx, __shfl_xor_sync(0xFFFFFFFFu, mx, off));
    float s = expf(v.x-mx)+expf(v.y-mx)+expf(v.z-mx)+expf(v.w-mx);
    #pragma unroll
    for (int off=16; off>0; off>>=1) s += __shfl_xor_sync(0xFFFFFFFFu, s, off);
    float lse = mx + logf(s);
    v.x -= lse; v.y -= lse; v.z -= lse; v.w -= lse;
    reinterpret_cast<float4*>(outp + (size_t)i*FF)[l] = v;
}

// ---------------- host ----------------
static void* symaddr(const void* s){ void* p = nullptr; cudaGetSymbolAddress(&p, s); return p; }

extern "C" void kernel_launch(void* const* d_in, const int* in_sizes, int n_in,
                              void* d_out, int out_size) {
    const float* x  = (const float*)d_in[0];
    const float* ew = (const float*)d_in[1];
    const float* W1 = (const float*)d_in[2];
    const float* b1 = (const float*)d_in[3];
    const float* W2 = (const float*)d_in[4];
    const float* b2 = (const float*)d_in[5];
    const int*   ei = (const int*)  d_in[6];
    const int* src = ei;
    const int* dst = ei + EE;
    float* outp = (float*)d_out;

    float*  feat = (float*)  symaddr(g_feat);
    float*  xp2  = (float*)  symaddr(g_xp2);
    __half* h_in = (__half*) symaddr(g_h_in);
    __half* h_z1 = (__half*) symaddr(g_h_z1);
    __half* h_z2 = (__half*) symaddr(g_h_z2);
    __half* Wh1  = (__half*) symaddr(g_Wh1);
    __half* Wh2  = (__half*) symaddr(g_Wh2);
    double* dgd1 = (double*) symaddr(g_degd1);
    double* dgd2 = (double*) symaddr(g_degd2);
    int*    cnt1 = (int*)    symaddr(g_cnt1);
    int*    cnt2 = (int*)    symaddr(g_cnt2);
    void*   hash = symaddr(g_hash);
    int*    c1   = (int*)    symaddr(g_c1);
    int*    c2   = (int*)    symaddr(g_c2);
    int*    s2   = (int*)    symaddr(g_s2);
    int*    d2   = (int*)    symaddr(g_d2);
    float*  w2   = (float*)  symaddr(g_w2);
    int*    rp1  = (int*)    symaddr(g_rp1);
    int*    rp2  = (int*)    symaddr(g_rp2);
    int*    col1 = (int*)    symaddr(g_col1);
    int*    col2 = (int*)    symaddr(g_col2);
    float*  val1 = (float*)  symaddr(g_val1);
    float*  val2 = (float*)  symaddr(g_val2);
    float*  di1  = (float*)  symaddr(g_dinv1);
    float*  di2  = (float*)  symaddr(g_dinv2);
    float*  dc1  = (float*)  symaddr(g_dcinv1);
    float*  dc2  = (float*)  symaddr(g_dcinv2);
    int*    pt1  = (int*)    symaddr(g_pt1);
    int*    pt2  = (int*)    symaddr(g_pt2);

    static cudaStream_t sB = nullptr, sC = nullptr;
    static cudaEvent_t evRoot, evPre, evFill, evC1, evB2, evCvt;
    if (!sB){
        cudaStreamCreate(&sB);
        cudaStreamCreate(&sC);
        cudaEventCreateWithFlags(&evRoot, cudaEventDisableTiming);
        cudaEventCreateWithFlags(&evPre,  cudaEventDisableTiming);
        cudaEventCreateWithFlags(&evFill, cudaEventDisableTiming);
        cudaEventCreateWithFlags(&evC1,  cudaEventDisableTiming);
        cudaEventCreateWithFlags(&evB2,  cudaEventDisableTiming);
        cudaEventCreateWithFlags(&evCvt, cudaEventDisableTiming);
        cudaFuncSetAttribute(k_gemm_mma, cudaFuncAttributeMaxDynamicSharedMemorySize, GEMM_SMEM);
    }

    const int EB = EE/256;
    const int NB = (NN+255)/256;
    const int PB = (NN*32+255)/256;
    const int GB = (NN+127)/128;
    const int CB = (NN*FF/4+255)/256;
    const int WB = (3*128*128/4+255)/256;

    // ===== fork point =====
    cudaMemsetAsync(cnt1, 0, NN*sizeof(int));
    cudaEventRecord(evRoot, 0);

    // ===== sC: degd/cnt2 memsets + fp16 mirrors =====
    cudaStreamWaitEvent(sC, evRoot, 0);
    cudaMemsetAsync(dgd1, 0, NN*sizeof(double), sC);
    cudaMemsetAsync(dgd2, 0, NN*sizeof(double), sC);
    cudaMemsetAsync(cnt2, 0, NN*sizeof(int), sC);
    cudaMemsetAsync(hash, 0xFF, HSIZE*sizeof(unsigned), sC);
    cudaEventRecord(evPre, sC);
    k_cvt<<<CB,256,0,sC>>>(x, h_in);
    k_cvtW<<<WB,256,0,sC>>>(W1, Wh1);
    k_cvtW<<<WB,256,0,sC>>>(W2, Wh2);
    cudaEventRecord(evCvt, sC);

    // ===== A: block-1 CSR build =====
    cudaStreamWaitEvent(0, evPre, 0);
    k_count<<<EB,256>>>(dst, ew, cnt1, dgd1);
    k_scan1<<<NB,256>>>(cnt1, dc1, rp1, dgd1, di1);
    k_scan2<<<1,256>>>();
    k_scan3<<<NB,256>>>(rp1, pt1);
    cudaMemsetAsync(cnt1, 0, NN*sizeof(int));
    k_fill<<<EB,256>>>(src, dst, ew, rp1, cnt1, dc1, di1, col1, val1);
    cudaEventRecord(evFill, 0);

    // ===== B: matching + pooled-graph CSR build (hidden) =====
    cudaStreamWaitEvent(sB, evPre, 0);
    cudaStreamWaitEvent(sB, evFill, 0);
    k_partner<<<EB,256,0,sB>>>(src, dst, pt1);
    k_cluster<<<NB,256,0,sB>>>(pt1, c1);
    cudaEventRecord(evC1, sB);
    k_pool_edges<<<EB,256,0,sB>>>(src, dst, cnt2, dgd2);   // fused count2/degd2
    k_scan1<<<NB,256,0,sB>>>(cnt2, dc2, rp2, dgd2, di2);
    k_scan2<<<1,256,0,sB>>>();
    k_scan3<<<NB,256,0,sB>>>(rp2, pt2);
    cudaMemsetAsync(cnt2, 0, NN*sizeof(int), sB);
    k_fill<<<EB,256,0,sB>>>(s2, d2, w2, rp2, cnt2, dc2, di2, col2, val2);
    k_partner<<<EB,256,0,sB>>>(s2, d2, pt2);
    k_cluster<<<NB,256,0,sB>>>(pt2, c2);
    cudaEventRecord(evB2, sB);

    // ===== A: block-1 heavy chain =====
    cudaStreamWaitEvent(0, evCvt, 0);
    k_prop_a<<<PB,256>>>(rp1, col1, val1, h_in, h_z1);
    k_prop_b<<<PB,256>>>(rp1, col1, val1, h_z1, h_in, h_z2);
    k_gemm_mma<<<GB,256,GEMM_SMEM>>>(h_in, h_z1, h_z2, Wh1, b1, feat);
    cudaStreamWaitEvent(0, evC1, 0);
    k_pool<<<PB,256>>>(pt1, feat, nullptr, h_in);

    // ===== A: block-2 heavy chain =====
    cudaStreamWaitEvent(0, evB2, 0);
    k_prop_a<<<PB,256>>>(rp2, col2, val2, h_in, h_z1);
    k_prop_b<<<PB,256>>>(rp2, col2, val2, h_z1, h_in, h_z2);
    k_gemm_mma<<<GB,256,GEMM_SMEM>>>(h_in, h_z1, h_z2, Wh2, b2, feat);
    k_pool<<<PB,256>>>(pt2, feat, xp2, nullptr);

    // ===== output =====
    k_smax_gather<<<PB,256>>>(outp);
}